// round 1
// baseline (speedup 1.0000x reference)
#include <cuda_runtime.h>
#include <math.h>

#define B_DIM 8
#define S_DIM 2048
#define H_DIM 512
#define NROWS (B_DIM * S_DIM)          // 16384

// ---------------- scratch (device globals; no allocations allowed) ----------
__device__ float g_pe[S_DIM * H_DIM];                      // 4 MB
__device__ float g_x [B_DIM * S_DIM * H_DIM];              // 32 MB
__device__ float g_q [B_DIM * S_DIM * H_DIM];              // 32 MB
__device__ float g_k [B_DIM * S_DIM * H_DIM];              // 32 MB
__device__ float g_v [B_DIM * S_DIM * H_DIM];              // 32 MB
__device__ float g_sc[B_DIM * S_DIM * S_DIM];              // 134 MB

// ---------------- positional encoding (fp64 for exact match) ----------------
__global__ void pe_kernel(float* __restrict__ pe) {
    int idx = blockIdx.x * blockDim.x + threadIdx.x;
    if (idx >= S_DIM * H_DIM) return;
    int h = idx & (H_DIM - 1);
    int s = idx >> 9;                       // H=512
    int j = (h < H_DIM / 2) ? h : h - H_DIM / 2;
    double d   = exp(-((double)(2 * j)) * (log(10000.0) / (double)H_DIM));
    double ang = (double)s * d;
    pe[idx] = (float)((h < H_DIM / 2) ? sin(ang) : cos(ang));
}

__global__ void add_pe_kernel(const float* __restrict__ in,
                              const float* __restrict__ pe,
                              float* __restrict__ x) {
    int i = blockIdx.x * blockDim.x + threadIdx.x;   // over float4 elements
    const int total4 = B_DIM * S_DIM * H_DIM / 4;
    if (i >= total4) return;
    const int pe4 = S_DIM * H_DIM / 4;
    float4 a = ((const float4*)in)[i];
    float4 p = ((const float4*)pe)[i % pe4];
    a.x += p.x; a.y += p.y; a.z += p.z; a.w += p.w;
    ((float4*)x)[i] = a;
}

// ---------------- SGEMM: C = A * B^T (+bias), A[M,K], B[N,K], C[M,N] --------
// 128x128 block tile, BK=8, 256 threads, 8x8 microtile.
__global__ __launch_bounds__(256)
void gemm_nt_kernel(const float* __restrict__ A, const float* __restrict__ Bm,
                    const float* __restrict__ bias, float* __restrict__ C,
                    int M, int N, int K,
                    long long sA, long long sB, long long sC) {
    const int BM = 128, BN = 128, BK = 8;
    __shared__ float As[BK][BM];
    __shared__ float Bs[BK][BN];

    const float* Ab = A  + (long long)blockIdx.z * sA;
    const float* Bb = Bm + (long long)blockIdx.z * sB;
    float*       Cb = C  + (long long)blockIdx.z * sC;

    int bm = blockIdx.y * BM;
    int bn = blockIdx.x * BN;
    int tid = threadIdx.x;
    int tx = tid & 15, ty = tid >> 4;

    float acc[8][8];
#pragma unroll
    for (int i = 0; i < 8; i++)
#pragma unroll
        for (int j = 0; j < 8; j++) acc[i][j] = 0.f;

    int a_row = tid >> 1, a_k = (tid & 1) * 4;     // one float4 per thread
    for (int k0 = 0; k0 < K; k0 += BK) {
        float4 va = *(const float4*)(Ab + (long long)(bm + a_row) * K + k0 + a_k);
        float4 vb = *(const float4*)(Bb + (long long)(bn + a_row) * K + k0 + a_k);
        As[a_k + 0][a_row] = va.x; As[a_k + 1][a_row] = va.y;
        As[a_k + 2][a_row] = va.z; As[a_k + 3][a_row] = va.w;
        Bs[a_k + 0][a_row] = vb.x; Bs[a_k + 1][a_row] = vb.y;
        Bs[a_k + 2][a_row] = vb.z; Bs[a_k + 3][a_row] = vb.w;
        __syncthreads();
#pragma unroll
        for (int kk = 0; kk < BK; kk++) {
            float a[8], b[8];
            *(float4*)&a[0] = *(const float4*)&As[kk][ty * 8];
            *(float4*)&a[4] = *(const float4*)&As[kk][ty * 8 + 4];
            *(float4*)&b[0] = *(const float4*)&Bs[kk][tx * 8];
            *(float4*)&b[4] = *(const float4*)&Bs[kk][tx * 8 + 4];
#pragma unroll
            for (int i = 0; i < 8; i++)
#pragma unroll
                for (int j = 0; j < 8; j++)
                    acc[i][j] = fmaf(a[i], b[j], acc[i][j]);
        }
        __syncthreads();
    }
#pragma unroll
    for (int i = 0; i < 8; i++) {
        int m = bm + ty * 8 + i;
#pragma unroll
        for (int j = 0; j < 8; j += 4) {
            int n = bn + tx * 8 + j;
            float4 v;
            float b0 = bias ? bias[n + 0] : 0.f;
            float b1 = bias ? bias[n + 1] : 0.f;
            float b2 = bias ? bias[n + 2] : 0.f;
            float b3 = bias ? bias[n + 3] : 0.f;
            v.x = acc[i][j + 0] + b0;
            v.y = acc[i][j + 1] + b1;
            v.z = acc[i][j + 2] + b2;
            v.w = acc[i][j + 3] + b3;
            *(float4*)(Cb + (long long)m * N + n) = v;
        }
    }
}

// ---------------- SGEMM: C = A * B, A[M,K], B[K,N], C[M,N] ------------------
__global__ __launch_bounds__(256)
void gemm_nn_kernel(const float* __restrict__ A, const float* __restrict__ Bm,
                    float* __restrict__ C,
                    int M, int N, int K,
                    long long sA, long long sB, long long sC) {
    const int BM = 128, BN = 128, BK = 8;
    __shared__ float As[BK][BM];
    __shared__ float Bs[BK][BN];

    const float* Ab = A  + (long long)blockIdx.z * sA;
    const float* Bb = Bm + (long long)blockIdx.z * sB;
    float*       Cb = C  + (long long)blockIdx.z * sC;

    int bm = blockIdx.y * BM;
    int bn = blockIdx.x * BN;
    int tid = threadIdx.x;
    int tx = tid & 15, ty = tid >> 4;

    float acc[8][8];
#pragma unroll
    for (int i = 0; i < 8; i++)
#pragma unroll
        for (int j = 0; j < 8; j++) acc[i][j] = 0.f;

    int a_row = tid >> 1, a_k = (tid & 1) * 4;       // A tile: 128 rows x 8 k
    int bk_row = tid >> 5, bk_col = (tid & 31) * 4;  // B tile: 8 rows x 128 n

    for (int k0 = 0; k0 < K; k0 += BK) {
        float4 va = *(const float4*)(Ab + (long long)(bm + a_row) * K + k0 + a_k);
        float4 vb = *(const float4*)(Bb + (long long)(k0 + bk_row) * N + bn + bk_col);
        As[a_k + 0][a_row] = va.x; As[a_k + 1][a_row] = va.y;
        As[a_k + 2][a_row] = va.z; As[a_k + 3][a_row] = va.w;
        *(float4*)&Bs[bk_row][bk_col] = vb;
        __syncthreads();
#pragma unroll
        for (int kk = 0; kk < BK; kk++) {
            float a[8], b[8];
            *(float4*)&a[0] = *(const float4*)&As[kk][ty * 8];
            *(float4*)&a[4] = *(const float4*)&As[kk][ty * 8 + 4];
            *(float4*)&b[0] = *(const float4*)&Bs[kk][tx * 8];
            *(float4*)&b[4] = *(const float4*)&Bs[kk][tx * 8 + 4];
#pragma unroll
            for (int i = 0; i < 8; i++)
#pragma unroll
                for (int j = 0; j < 8; j++)
                    acc[i][j] = fmaf(a[i], b[j], acc[i][j]);
        }
        __syncthreads();
    }
#pragma unroll
    for (int i = 0; i < 8; i++) {
        int m = bm + ty * 8 + i;
#pragma unroll
        for (int j = 0; j < 8; j += 4) {
            int n = bn + tx * 8 + j;
            float4 v;
            v.x = acc[i][j + 0]; v.y = acc[i][j + 1];
            v.z = acc[i][j + 2]; v.w = acc[i][j + 3];
            *(float4*)(Cb + (long long)m * N + n) = v;
        }
    }
}

// ---------------- row softmax over 2048 columns -----------------------------
__global__ __launch_bounds__(256)
void softmax_kernel(float* __restrict__ scores) {
    float* row = scores + (long long)blockIdx.x * S_DIM;
    int tid = threadIdx.x;
    __shared__ float red[256];

    float vals[8];
    float m = -INFINITY;
#pragma unroll
    for (int i = 0; i < 8; i++) {
        vals[i] = row[tid + i * 256];
        m = fmaxf(m, vals[i]);
    }
    red[tid] = m; __syncthreads();
    for (int s = 128; s > 0; s >>= 1) {
        if (tid < s) red[tid] = fmaxf(red[tid], red[tid + s]);
        __syncthreads();
    }
    m = red[0]; __syncthreads();

    float sum = 0.f;
#pragma unroll
    for (int i = 0; i < 8; i++) {
        vals[i] = expf(vals[i] - m);
        sum += vals[i];
    }
    red[tid] = sum; __syncthreads();
    for (int s = 128; s > 0; s >>= 1) {
        if (tid < s) red[tid] += red[tid + s];
        __syncthreads();
    }
    float inv = 1.f / red[0];
#pragma unroll
    for (int i = 0; i < 8; i++) row[tid + i * 256] = vals[i] * inv;
}

// ---------------- launch ----------------------------------------------------
extern "C" void kernel_launch(void* const* d_in, const int* in_sizes, int n_in,
                              void* d_out, int out_size) {
    const float* in_e = (const float*)d_in[0];
    const float* Wq   = (const float*)d_in[1];
    const float* bq   = (const float*)d_in[2];
    const float* Wk   = (const float*)d_in[3];
    const float* bk   = (const float*)d_in[4];
    const float* Wv   = (const float*)d_in[5];
    const float* bv   = (const float*)d_in[6];
    float* out = (float*)d_out;

    float *pe, *x, *q, *k, *v, *sc;
    cudaGetSymbolAddress((void**)&pe, g_pe);
    cudaGetSymbolAddress((void**)&x,  g_x);
    cudaGetSymbolAddress((void**)&q,  g_q);
    cudaGetSymbolAddress((void**)&k,  g_k);
    cudaGetSymbolAddress((void**)&v,  g_v);
    cudaGetSymbolAddress((void**)&sc, g_sc);

    // 1) positional encoding + add
    pe_kernel<<<(S_DIM * H_DIM + 255) / 256, 256>>>(pe);
    int n4 = B_DIM * S_DIM * H_DIM / 4;
    add_pe_kernel<<<(n4 + 255) / 256, 256>>>(in_e, pe, x);

    // 2) Q,K,V projections: [16384,512] = x[16384,512] @ W[512,512]^T + b
    dim3 gqkv(H_DIM / 128, NROWS / 128, 1);
    gemm_nt_kernel<<<gqkv, 256>>>(x, Wq, bq, q, NROWS, H_DIM, H_DIM, 0, 0, 0);
    gemm_nt_kernel<<<gqkv, 256>>>(x, Wk, bk, k, NROWS, H_DIM, H_DIM, 0, 0, 0);
    gemm_nt_kernel<<<gqkv, 256>>>(x, Wv, bv, v, NROWS, H_DIM, H_DIM, 0, 0, 0);

    // 3) scores = q @ k^T  (batched over B)
    dim3 gsc(S_DIM / 128, S_DIM / 128, B_DIM);
    gemm_nt_kernel<<<gsc, 256>>>(q, k, nullptr, sc,
                                 S_DIM, S_DIM, H_DIM,
                                 (long long)S_DIM * H_DIM,
                                 (long long)S_DIM * H_DIM,
                                 (long long)S_DIM * S_DIM);

    // 4) softmax over last dim
    softmax_kernel<<<B_DIM * S_DIM, 256>>>(sc);

    // 5) out = weights @ v  (batched over B)
    dim3 gout(H_DIM / 128, S_DIM / 128, B_DIM);
    gemm_nn_kernel<<<gout, 256>>>(sc, v, out,
                                  S_DIM, H_DIM, S_DIM,
                                  (long long)S_DIM * S_DIM,
                                  (long long)S_DIM * H_DIM,
                                  (long long)S_DIM * H_DIM);
}

// round 3
// speedup vs baseline: 2.0122x; 2.0122x over previous
#include <cuda_runtime.h>
#include <cuda_bf16.h>
#include <cstdint>
#include <math.h>

#define B_DIM 8
#define S_DIM 2048
#define H_DIM 512
#define NROWS (B_DIM * S_DIM)          // 16384

// ---------------- scratch (device globals; no allocations allowed) ----------
__device__ float g_pe[S_DIM * H_DIM];
__device__ __nv_bfloat16 g_xh[NROWS * H_DIM], g_xl[NROWS * H_DIM];
__device__ __nv_bfloat16 g_wqh[H_DIM * H_DIM], g_wql[H_DIM * H_DIM];
__device__ __nv_bfloat16 g_wkh[H_DIM * H_DIM], g_wkl[H_DIM * H_DIM];
__device__ __nv_bfloat16 g_wvh[H_DIM * H_DIM], g_wvl[H_DIM * H_DIM];
__device__ __nv_bfloat16 g_qh[NROWS * H_DIM], g_ql[NROWS * H_DIM];
__device__ __nv_bfloat16 g_kh[NROWS * H_DIM], g_kl[NROWS * H_DIM];
__device__ __nv_bfloat16 g_vth[H_DIM * NROWS], g_vtl[H_DIM * NROWS];   // v transposed
__device__ float g_sc[(long long)B_DIM * S_DIM * S_DIM];               // 134 MB
__device__ __nv_bfloat16 g_ph[(long long)B_DIM * S_DIM * S_DIM];
__device__ __nv_bfloat16 g_pl[(long long)B_DIM * S_DIM * S_DIM];

// ---------------- helpers ----------------------------------------------
__device__ __forceinline__ uint32_t smem_u32(const void* p) {
    uint32_t a;
    asm("{ .reg .u64 t; cvta.to.shared.u64 t, %1; cvt.u32.u64 %0, t; }" : "=r"(a) : "l"(p));
    return a;
}
__device__ __forceinline__ void cp16(uint32_t dst, const void* src) {
    asm volatile("cp.async.cg.shared.global [%0], [%1], 16;"
                 :: "r"(dst), "l"(__cvta_generic_to_global(src)));
}
#define CP_COMMIT() asm volatile("cp.async.commit_group;" ::: "memory")
#define CP_WAIT_1() asm volatile("cp.async.wait_group 1;" ::: "memory")
#define CP_WAIT_0() asm volatile("cp.async.wait_group 0;" ::: "memory")

__device__ __forceinline__ void ldsm4(uint32_t& r0, uint32_t& r1, uint32_t& r2, uint32_t& r3,
                                      uint32_t addr) {
    asm volatile("ldmatrix.sync.aligned.m8n8.x4.shared.b16 {%0,%1,%2,%3}, [%4];"
                 : "=r"(r0), "=r"(r1), "=r"(r2), "=r"(r3) : "r"(addr));
}
__device__ __forceinline__ void mma16816(float* c, const uint32_t* a, const uint32_t* b) {
    asm volatile(
        "mma.sync.aligned.m16n8k16.row.col.f32.bf16.bf16.f32 "
        "{%0,%1,%2,%3}, {%4,%5,%6,%7}, {%8,%9}, {%0,%1,%2,%3};"
        : "+f"(c[0]), "+f"(c[1]), "+f"(c[2]), "+f"(c[3])
        : "r"(a[0]), "r"(a[1]), "r"(a[2]), "r"(a[3]), "r"(b[0]), "r"(b[1]));
}
__device__ __forceinline__ void split2(float v, unsigned short& h, unsigned short& l) {
    __nv_bfloat16 hb = __float2bfloat16(v);
    __nv_bfloat16 lb = __float2bfloat16(v - __bfloat162float(hb));
    h = __bfloat16_as_ushort(hb);
    l = __bfloat16_as_ushort(lb);
}

// ---------------- split-bf16 HMMA GEMM: C = A * B^T -------------------------
// A[M,K], B[N,K] K-major bf16 hi/lo. 128x128 tile, BK=32, 256 thr, warp 32x64.
struct GemmParams {
    const __nv_bfloat16 *Ah, *Al, *Bh, *Bl;
    const float* bias;
    long long aBatch, bBatch;
    int aRow, bRow;
    int K;
    void* out0; void* out1;
    long long oBatch;
    int oRow;
    int mode;   // 0=bias+hi/lo, 1=bias+hi/lo transposed, 2=fp32
};

#define STAGE_BYTES 32768            // 4 tiles (Ah,Al,Bh,Bl) x 8KB
#define SMEM_DYN    (2 * STAGE_BYTES)
// tile row layout: 128 rows x 64B (32 bf16), chunk c(16B) swizzled: c ^ (row&3)

__global__ __launch_bounds__(256, 1) void tc_gemm(GemmParams p) {
    extern __shared__ char smem[];
    uint32_t sbase = smem_u32(smem);

    const int tid = threadIdx.x;
    const int wid = tid >> 5, lane = tid & 31;
    const int wm = wid & 3, wn = wid >> 2;          // warp tile (wm*32, wn*64)

    const int bm = blockIdx.y * 128, bn = blockIdx.x * 128, z = blockIdx.z;
    const __nv_bfloat16* Ah = p.Ah + (long long)z * p.aBatch;
    const __nv_bfloat16* Al = p.Al + (long long)z * p.aBatch;
    const __nv_bfloat16* Bh = p.Bh + (long long)z * p.bBatch;
    const __nv_bfloat16* Bl = p.Bl + (long long)z * p.bBatch;

    const int nc = p.K >> 5;   // chunks of 32

    auto load_chunk = [&](int c, int s) {
        uint32_t stBase = sbase + s * STAGE_BYTES;
        long long kofs = (long long)c * 32;
#pragma unroll
        for (int t = 0; t < 4; t++) {
            const __nv_bfloat16* src;
            int rbase, rstride;
            if (t == 0)      { src = Ah; rbase = bm; rstride = p.aRow; }
            else if (t == 1) { src = Al; rbase = bm; rstride = p.aRow; }
            else if (t == 2) { src = Bh; rbase = bn; rstride = p.bRow; }
            else             { src = Bl; rbase = bn; rstride = p.bRow; }
#pragma unroll
            for (int it = 0; it < 2; it++) {
                int u = tid + it * 256;              // 512 chunk units
                int row = u >> 2, ch = u & 3;
                const void* g = src + (long long)(rbase + row) * rstride + kofs + ch * 8;
                uint32_t off = row * 64 + ((ch ^ (row & 3)) << 4);
                cp16(stBase + t * 8192 + off, g);
            }
        }
        CP_COMMIT();
    };

    float acc[2][8][4];
#pragma unroll
    for (int i = 0; i < 2; i++)
#pragma unroll
        for (int j = 0; j < 8; j++)
#pragma unroll
            for (int r = 0; r < 4; r++) acc[i][j][r] = 0.f;

    load_chunk(0, 0);
    if (nc > 1) load_chunk(1, 1);

    for (int c = 0; c < nc; c++) {
        int s = c & 1;
        if (c == nc - 1) CP_WAIT_0(); else CP_WAIT_1();
        __syncthreads();

        uint32_t st = sbase + s * STAGE_BYTES;
        uint32_t aHB = st, aLB = st + 8192, bHB = st + 16384, bLB = st + 24576;

#pragma unroll
        for (int ks = 0; ks < 2; ks++) {
            // A fragments: 2 m16 tiles, hi+lo
            uint32_t ah[2][4], al[2][4];
#pragma unroll
            for (int t = 0; t < 2; t++) {
                int row = wm * 32 + t * 16 + (lane & 15);
                int ch = ks * 2 + (lane >> 4);
                uint32_t off = row * 64 + (((ch ^ (row & 3))) << 4);
                ldsm4(ah[t][0], ah[t][1], ah[t][2], ah[t][3], aHB + off);
                ldsm4(al[t][0], al[t][1], al[t][2], al[t][3], aLB + off);
            }
            // B fragments: 8 n8 tiles (4 x4 loads), hi+lo
            uint32_t bh[8][2], bl[8][2];
#pragma unroll
            for (int jj = 0; jj < 4; jj++) {
                int row = wn * 64 + jj * 16 + (lane & 15);
                int ch = ks * 2 + (lane >> 4);
                uint32_t off = row * 64 + (((ch ^ (row & 3))) << 4);
                uint32_t r0, r1, r2, r3;
                ldsm4(r0, r1, r2, r3, bHB + off);
                bh[jj * 2][0] = r0; bh[jj * 2][1] = r2;
                bh[jj * 2 + 1][0] = r1; bh[jj * 2 + 1][1] = r3;
                ldsm4(r0, r1, r2, r3, bLB + off);
                bl[jj * 2][0] = r0; bl[jj * 2][1] = r2;
                bl[jj * 2 + 1][0] = r1; bl[jj * 2 + 1][1] = r3;
            }
#pragma unroll
            for (int i = 0; i < 2; i++)
#pragma unroll
                for (int j = 0; j < 8; j++) {
                    mma16816(acc[i][j], ah[i], bh[j]);
                    mma16816(acc[i][j], ah[i], bl[j]);
                    mma16816(acc[i][j], al[i], bh[j]);
                }
        }
        __syncthreads();
        if (c + 2 < nc) load_chunk(c + 2, s);
    }

    // --------- epilogue (direct register->global) ---------
    const int mB = bm + wm * 32 + (lane >> 2);
    const int nB = bn + wn * 64 + (lane & 3) * 2;

    if (p.mode == 2) {
        float* o0 = (float*)p.out0 + (long long)z * p.oBatch;
#pragma unroll
        for (int i = 0; i < 2; i++)
#pragma unroll
            for (int j = 0; j < 8; j++) {
                int m = mB + i * 16, n = nB + j * 8;
                *(float2*)(o0 + (long long)m * p.oRow + n)       = make_float2(acc[i][j][0], acc[i][j][1]);
                *(float2*)(o0 + (long long)(m + 8) * p.oRow + n) = make_float2(acc[i][j][2], acc[i][j][3]);
            }
    } else if (p.mode == 0) {
        __nv_bfloat16* o0 = (__nv_bfloat16*)p.out0;
        __nv_bfloat16* o1 = (__nv_bfloat16*)p.out1;
#pragma unroll
        for (int i = 0; i < 2; i++)
#pragma unroll
            for (int j = 0; j < 8; j++) {
                int m = mB + i * 16, n = nB + j * 8;
                float b0 = p.bias[n], b1 = p.bias[n + 1];
                unsigned short h0, l0, h1, l1;
#pragma unroll
                for (int half = 0; half < 2; half++) {
                    int mm = m + half * 8;
                    split2(acc[i][j][half * 2 + 0] + b0, h0, l0);
                    split2(acc[i][j][half * 2 + 1] + b1, h1, l1);
                    long long a = (long long)mm * p.oRow + n;
                    *(ushort2*)(o0 + a) = make_ushort2(h0, h1);
                    *(ushort2*)(o1 + a) = make_ushort2(l0, l1);
                }
            }
    } else {  // mode 1: transposed hi/lo (vT)
        __nv_bfloat16* o0 = (__nv_bfloat16*)p.out0;
        __nv_bfloat16* o1 = (__nv_bfloat16*)p.out1;
#pragma unroll
        for (int i = 0; i < 2; i++)
#pragma unroll
            for (int j = 0; j < 8; j++) {
                int m = mB + i * 16, n = nB + j * 8;
#pragma unroll
                for (int r = 0; r < 4; r++) {
                    int mm = m + (r >> 1) * 8;
                    int nn = n + (r & 1);
                    float v = acc[i][j][r] + p.bias[nn];
                    unsigned short h, l;
                    split2(v, h, l);
                    long long a = (long long)nn * p.oRow + mm;
                    o0[a] = __ushort_as_bfloat16(h);
                    o1[a] = __ushort_as_bfloat16(l);
                }
            }
    }
}

// ---------------- positional encoding ---------------------------------------
__global__ void pe_kernel(float* __restrict__ pe) {
    int idx = blockIdx.x * blockDim.x + threadIdx.x;
    if (idx >= S_DIM * H_DIM) return;
    int h = idx & (H_DIM - 1);
    int s = idx >> 9;
    int j = (h < H_DIM / 2) ? h : h - H_DIM / 2;
    double d   = exp(-((double)(2 * j)) * (log(10000.0) / (double)H_DIM));
    double ang = (double)s * d;
    pe[idx] = (float)((h < H_DIM / 2) ? sin(ang) : cos(ang));
}

__global__ void conv_x_kernel(const float* __restrict__ in, const float* __restrict__ pe,
                              __nv_bfloat16* __restrict__ xh, __nv_bfloat16* __restrict__ xl) {
    int i = blockIdx.x * blockDim.x + threadIdx.x;
    if (i >= NROWS * H_DIM) return;
    float v = in[i] + pe[i & (S_DIM * H_DIM - 1)];
    unsigned short h, l;
    split2(v, h, l);
    xh[i] = __ushort_as_bfloat16(h);
    xl[i] = __ushort_as_bfloat16(l);
}

__global__ void conv_w_kernel(const float* __restrict__ w,
                              __nv_bfloat16* __restrict__ wh, __nv_bfloat16* __restrict__ wl) {
    int i = blockIdx.x * blockDim.x + threadIdx.x;
    if (i >= H_DIM * H_DIM) return;
    unsigned short h, l;
    split2(w[i], h, l);
    wh[i] = __ushort_as_bfloat16(h);
    wl[i] = __ushort_as_bfloat16(l);
}

// ---------------- softmax: fp32 in, bf16 hi/lo out ---------------------------
__global__ __launch_bounds__(256) void softmax_kernel(const float* __restrict__ sc,
                                                      __nv_bfloat16* __restrict__ ph,
                                                      __nv_bfloat16* __restrict__ pl) {
    const float* row = sc + (long long)blockIdx.x * S_DIM;
    long long obase = (long long)blockIdx.x * S_DIM;
    int tid = threadIdx.x;
    __shared__ float red[256];

    float vals[8];
    float m = -INFINITY;
#pragma unroll
    for (int i = 0; i < 8; i++) { vals[i] = row[tid + i * 256]; m = fmaxf(m, vals[i]); }
    red[tid] = m; __syncthreads();
    for (int s = 128; s > 0; s >>= 1) {
        if (tid < s) red[tid] = fmaxf(red[tid], red[tid + s]);
        __syncthreads();
    }
    m = red[0]; __syncthreads();

    float sum = 0.f;
#pragma unroll
    for (int i = 0; i < 8; i++) { vals[i] = expf(vals[i] - m); sum += vals[i]; }
    red[tid] = sum; __syncthreads();
    for (int s = 128; s > 0; s >>= 1) {
        if (tid < s) red[tid] += red[tid + s];
        __syncthreads();
    }
    float inv = 1.f / red[0];
#pragma unroll
    for (int i = 0; i < 8; i++) {
        float w = vals[i] * inv;
        unsigned short h, l;
        split2(w, h, l);
        ph[obase + tid + i * 256] = __ushort_as_bfloat16(h);
        pl[obase + tid + i * 256] = __ushort_as_bfloat16(l);
    }
}

// ---------------- launch ----------------------------------------------------
extern "C" void kernel_launch(void* const* d_in, const int* in_sizes, int n_in,
                              void* d_out, int out_size) {
    const float* in_e = (const float*)d_in[0];
    const float* Wq   = (const float*)d_in[1];
    const float* bq   = (const float*)d_in[2];
    const float* Wk   = (const float*)d_in[3];
    const float* bk   = (const float*)d_in[4];
    const float* Wv   = (const float*)d_in[5];
    const float* bv   = (const float*)d_in[6];
    float* out = (float*)d_out;

    cudaFuncSetAttribute(tc_gemm, cudaFuncAttributeMaxDynamicSharedMemorySize, SMEM_DYN);

#define SYM(v, s) void* v##_; cudaGetSymbolAddress(&v##_, s);
    SYM(pe, g_pe) SYM(xh, g_xh) SYM(xl, g_xl)
    SYM(wqh, g_wqh) SYM(wql, g_wql) SYM(wkh, g_wkh) SYM(wkl, g_wkl)
    SYM(wvh, g_wvh) SYM(wvl, g_wvl)
    SYM(qh, g_qh) SYM(ql, g_ql) SYM(kh, g_kh) SYM(kl, g_kl)
    SYM(vth, g_vth) SYM(vtl, g_vtl)
    SYM(sc, g_sc) SYM(sph, g_ph) SYM(spl, g_pl)
#undef SYM

    pe_kernel<<<(S_DIM * H_DIM + 255) / 256, 256>>>((float*)pe_);
    conv_x_kernel<<<(NROWS * H_DIM + 255) / 256, 256>>>(in_e, (float*)pe_,
        (__nv_bfloat16*)xh_, (__nv_bfloat16*)xl_);
    conv_w_kernel<<<(H_DIM * H_DIM + 255) / 256, 256>>>(Wq, (__nv_bfloat16*)wqh_, (__nv_bfloat16*)wql_);
    conv_w_kernel<<<(H_DIM * H_DIM + 255) / 256, 256>>>(Wk, (__nv_bfloat16*)wkh_, (__nv_bfloat16*)wkl_);
    conv_w_kernel<<<(H_DIM * H_DIM + 255) / 256, 256>>>(Wv, (__nv_bfloat16*)wvh_, (__nv_bfloat16*)wvl_);

    GemmParams p;
    // Q/K projections: M=16384, N=512, K=512 (mode 0)
    p.Ah = (const __nv_bfloat16*)xh_; p.Al = (const __nv_bfloat16*)xl_;
    p.aBatch = 0; p.bBatch = 0; p.aRow = H_DIM; p.bRow = H_DIM; p.K = H_DIM;
    p.oBatch = 0; p.oRow = H_DIM; p.mode = 0;
    dim3 gq(H_DIM / 128, NROWS / 128, 1);

    p.Bh = (const __nv_bfloat16*)wqh_; p.Bl = (const __nv_bfloat16*)wql_;
    p.bias = bq; p.out0 = qh_; p.out1 = ql_;
    tc_gemm<<<gq, 256, SMEM_DYN>>>(p);

    p.Bh = (const __nv_bfloat16*)wkh_; p.Bl = (const __nv_bfloat16*)wkl_;
    p.bias = bk; p.out0 = kh_; p.out1 = kl_;
    tc_gemm<<<gq, 256, SMEM_DYN>>>(p);

    // V projection, transposed output vT[512][16384] (mode 1)
    p.Bh = (const __nv_bfloat16*)wvh_; p.Bl = (const __nv_bfloat16*)wvl_;
    p.bias = bv; p.out0 = vth_; p.out1 = vtl_;
    p.oRow = NROWS; p.mode = 1;
    tc_gemm<<<gq, 256, SMEM_DYN>>>(p);

    // scores = q @ k^T per batch (mode 2)
    p.Ah = (const __nv_bfloat16*)qh_; p.Al = (const __nv_bfloat16*)ql_;
    p.Bh = (const __nv_bfloat16*)kh_; p.Bl = (const __nv_bfloat16*)kl_;
    p.bias = nullptr;
    p.aBatch = (long long)S_DIM * H_DIM; p.bBatch = (long long)S_DIM * H_DIM;
    p.aRow = H_DIM; p.bRow = H_DIM; p.K = H_DIM;
    p.out0 = sc_; p.out1 = nullptr;
    p.oBatch = (long long)S_DIM * S_DIM; p.oRow = S_DIM; p.mode = 2;
    dim3 gs(S_DIM / 128, S_DIM / 128, B_DIM);
    tc_gemm<<<gs, 256, SMEM_DYN>>>(p);

    // softmax -> bf16 hi/lo probs
    softmax_kernel<<<B_DIM * S_DIM, 256>>>((const float*)sc_,
        (__nv_bfloat16*)sph_, (__nv_bfloat16*)spl_);

    // out = probs @ v : NT with B = vT (mode 2 fp32 out)
    p.Ah = (const __nv_bfloat16*)sph_; p.Al = (const __nv_bfloat16*)spl_;
    p.Bh = (const __nv_bfloat16*)vth_; p.Bl = (const __nv_bfloat16*)vtl_;
    p.bias = nullptr;
    p.aBatch = (long long)S_DIM * S_DIM; p.bBatch = S_DIM;
    p.aRow = S_DIM; p.bRow = NROWS; p.K = S_DIM;
    p.out0 = out; p.out1 = nullptr;
    p.oBatch = (long long)S_DIM * H_DIM; p.oRow = H_DIM; p.mode = 2;
    dim3 go(H_DIM / 128, S_DIM / 128, B_DIM);
    tc_gemm<<<go, 256, SMEM_DYN>>>(p);
}

// round 4
// speedup vs baseline: 2.1606x; 1.0738x over previous
#include <cuda_runtime.h>
#include <cuda_bf16.h>
#include <cstdint>
#include <math.h>

#define B_DIM 8
#define S_DIM 2048
#define H_DIM 512
#define NROWS (B_DIM * S_DIM)          // 16384

// ---------------- scratch (device globals; no allocations allowed) ----------
__device__ float g_pe[S_DIM * H_DIM];
__device__ __nv_bfloat16 g_xh[NROWS * H_DIM], g_xl[NROWS * H_DIM];
__device__ __nv_bfloat16 g_wqh[H_DIM * H_DIM], g_wql[H_DIM * H_DIM];
__device__ __nv_bfloat16 g_wkh[H_DIM * H_DIM], g_wkl[H_DIM * H_DIM];
__device__ __nv_bfloat16 g_wvh[H_DIM * H_DIM], g_wvl[H_DIM * H_DIM];
__device__ __nv_bfloat16 g_qh[NROWS * H_DIM], g_ql[NROWS * H_DIM];
__device__ __nv_bfloat16 g_kh[NROWS * H_DIM], g_kl[NROWS * H_DIM];
__device__ __nv_bfloat16 g_vth[H_DIM * NROWS], g_vtl[H_DIM * NROWS];   // v transposed
__device__ float g_sc[(long long)B_DIM * S_DIM * S_DIM];               // 134 MB
__device__ __nv_bfloat16 g_ph[(long long)B_DIM * S_DIM * S_DIM];
__device__ __nv_bfloat16 g_pl[(long long)B_DIM * S_DIM * S_DIM];

// ---------------- helpers ----------------------------------------------
__device__ __forceinline__ uint32_t smem_u32(const void* p) {
    uint32_t a;
    asm("{ .reg .u64 t; cvta.to.shared.u64 t, %1; cvt.u32.u64 %0, t; }" : "=r"(a) : "l"(p));
    return a;
}
__device__ __forceinline__ void cp16(uint32_t dst, const void* src) {
    asm volatile("cp.async.cg.shared.global [%0], [%1], 16;"
                 :: "r"(dst), "l"(__cvta_generic_to_global(src)));
}
#define CP_COMMIT() asm volatile("cp.async.commit_group;" ::: "memory")
#define CP_WAIT_1() asm volatile("cp.async.wait_group 1;" ::: "memory")
#define CP_WAIT_0() asm volatile("cp.async.wait_group 0;" ::: "memory")

__device__ __forceinline__ void ldsm4(uint32_t& r0, uint32_t& r1, uint32_t& r2, uint32_t& r3,
                                      uint32_t addr) {
    asm volatile("ldmatrix.sync.aligned.m8n8.x4.shared.b16 {%0,%1,%2,%3}, [%4];"
                 : "=r"(r0), "=r"(r1), "=r"(r2), "=r"(r3) : "r"(addr));
}
__device__ __forceinline__ void mma16816(float* c, const uint32_t* a, const uint32_t* b) {
    asm volatile(
        "mma.sync.aligned.m16n8k16.row.col.f32.bf16.bf16.f32 "
        "{%0,%1,%2,%3}, {%4,%5,%6,%7}, {%8,%9}, {%0,%1,%2,%3};"
        : "+f"(c[0]), "+f"(c[1]), "+f"(c[2]), "+f"(c[3])
        : "r"(a[0]), "r"(a[1]), "r"(a[2]), "r"(a[3]), "r"(b[0]), "r"(b[1]));
}
__device__ __forceinline__ void split2(float v, unsigned short& h, unsigned short& l) {
    __nv_bfloat16 hb = __float2bfloat16(v);
    __nv_bfloat16 lb = __float2bfloat16(v - __bfloat162float(hb));
    h = __bfloat16_as_ushort(hb);
    l = __bfloat16_as_ushort(lb);
}

// ---------------- split-bf16 HMMA GEMM: C = A * B^T -------------------------
// A[M,K], B[N,K] K-major bf16 hi/lo. 128x128 tile, BK=32, 256 thr, warp 32x64.
// SMEM tile: 128 rows x 80B pitch (64B data + 16B pad) -> conflict-free ldsm.
struct GemmParams {
    const __nv_bfloat16 *Ah, *Al, *Bh, *Bl;
    const float* bias;
    long long aBatch, bBatch;
    int aRow, bRow;
    int K;
    void* out0; void* out1;
    long long oBatch;
    int oRow;
    int mode;   // 0=bias+hi/lo, 1=bias+hi/lo transposed, 2=fp32
};

#define ROW_PITCH   80
#define TILE_BYTES  (128 * ROW_PITCH)       // 10240
#define STAGE_BYTES (4 * TILE_BYTES)        // 40960 (Ah,Al,Bh,Bl)
#define SMEM_DYN    (2 * STAGE_BYTES)       // 81920

__global__ __launch_bounds__(256, 2) void tc_gemm(GemmParams p) {
    extern __shared__ char smem[];
    uint32_t sbase = smem_u32(smem);

    const int tid = threadIdx.x;
    const int wid = tid >> 5, lane = tid & 31;
    const int wm = wid & 3, wn = wid >> 2;          // warp tile (wm*32, wn*64)

    const int bm = blockIdx.y * 128, bn = blockIdx.x * 128, z = blockIdx.z;
    const __nv_bfloat16* Ah = p.Ah + (long long)z * p.aBatch;
    const __nv_bfloat16* Al = p.Al + (long long)z * p.aBatch;
    const __nv_bfloat16* Bh = p.Bh + (long long)z * p.bBatch;
    const __nv_bfloat16* Bl = p.Bl + (long long)z * p.bBatch;

    const int nc = p.K >> 5;   // chunks of 32

    auto load_chunk = [&](int c, int s) {
        uint32_t stBase = sbase + s * STAGE_BYTES;
        long long kofs = (long long)c * 32;
#pragma unroll
        for (int t = 0; t < 4; t++) {
            const __nv_bfloat16* src;
            int rbase, rstride;
            if (t == 0)      { src = Ah; rbase = bm; rstride = p.aRow; }
            else if (t == 1) { src = Al; rbase = bm; rstride = p.aRow; }
            else if (t == 2) { src = Bh; rbase = bn; rstride = p.bRow; }
            else             { src = Bl; rbase = bn; rstride = p.bRow; }
#pragma unroll
            for (int it = 0; it < 2; it++) {
                int u = tid + it * 256;              // 512 chunk units
                int row = u >> 2, ch = u & 3;
                const void* g = src + (long long)(rbase + row) * rstride + kofs + ch * 8;
                uint32_t off = row * ROW_PITCH + ch * 16;
                cp16(stBase + t * TILE_BYTES + off, g);
            }
        }
        CP_COMMIT();
    };

    float acc[2][8][4];
#pragma unroll
    for (int i = 0; i < 2; i++)
#pragma unroll
        for (int j = 0; j < 8; j++)
#pragma unroll
            for (int r = 0; r < 4; r++) acc[i][j][r] = 0.f;

    load_chunk(0, 0);
    if (nc > 1) load_chunk(1, 1);

    for (int c = 0; c < nc; c++) {
        int s = c & 1;
        if (c == nc - 1) CP_WAIT_0(); else CP_WAIT_1();
        __syncthreads();

        uint32_t st = sbase + s * STAGE_BYTES;
        uint32_t aHB = st, aLB = st + TILE_BYTES;
        uint32_t bHB = st + 2 * TILE_BYTES, bLB = st + 3 * TILE_BYTES;

#pragma unroll
        for (int ks = 0; ks < 2; ks++) {
            const int chcol = (ks * 2 + (lane >> 4)) * 16;
            // A fragments: 2 m16 tiles, hi+lo
            uint32_t ah[2][4], al[2][4];
#pragma unroll
            for (int t = 0; t < 2; t++) {
                int row = wm * 32 + t * 16 + (lane & 15);
                uint32_t off = row * ROW_PITCH + chcol;
                ldsm4(ah[t][0], ah[t][1], ah[t][2], ah[t][3], aHB + off);
                ldsm4(al[t][0], al[t][1], al[t][2], al[t][3], aLB + off);
            }
            // process B in two halves of 4 j-tiles to cap live registers
#pragma unroll
            for (int jh = 0; jh < 2; jh++) {
                uint32_t bh[4][2], bl[4][2];
#pragma unroll
                for (int jj = 0; jj < 2; jj++) {
                    int row = wn * 64 + (jh * 2 + jj) * 16 + (lane & 15);
                    uint32_t off = row * ROW_PITCH + chcol;
                    uint32_t r0, r1, r2, r3;
                    ldsm4(r0, r1, r2, r3, bHB + off);
                    bh[jj * 2][0] = r0; bh[jj * 2][1] = r2;
                    bh[jj * 2 + 1][0] = r1; bh[jj * 2 + 1][1] = r3;
                    ldsm4(r0, r1, r2, r3, bLB + off);
                    bl[jj * 2][0] = r0; bl[jj * 2][1] = r2;
                    bl[jj * 2 + 1][0] = r1; bl[jj * 2 + 1][1] = r3;
                }
#pragma unroll
                for (int i = 0; i < 2; i++)
#pragma unroll
                    for (int j4 = 0; j4 < 4; j4++) {
                        float* a = acc[i][jh * 4 + j4];
                        mma16816(a, ah[i], bh[j4]);
                        mma16816(a, ah[i], bl[j4]);
                        mma16816(a, al[i], bh[j4]);
                    }
            }
        }
        __syncthreads();
        if (c + 2 < nc) load_chunk(c + 2, s);
    }

    // --------- epilogue ---------
    const int mB = bm + wm * 32 + (lane >> 2);
    const int nB = bn + wn * 64 + (lane & 3) * 2;

    if (p.mode == 2) {
        float* o0 = (float*)p.out0 + (long long)z * p.oBatch;
#pragma unroll
        for (int i = 0; i < 2; i++)
#pragma unroll
            for (int j = 0; j < 8; j++) {
                int m = mB + i * 16, n = nB + j * 8;
                *(float2*)(o0 + (long long)m * p.oRow + n)       = make_float2(acc[i][j][0], acc[i][j][1]);
                *(float2*)(o0 + (long long)(m + 8) * p.oRow + n) = make_float2(acc[i][j][2], acc[i][j][3]);
            }
    } else if (p.mode == 0) {
        __nv_bfloat16* o0 = (__nv_bfloat16*)p.out0;
        __nv_bfloat16* o1 = (__nv_bfloat16*)p.out1;
#pragma unroll
        for (int i = 0; i < 2; i++)
#pragma unroll
            for (int j = 0; j < 8; j++) {
                int m = mB + i * 16, n = nB + j * 8;
                float b0 = p.bias[n], b1 = p.bias[n + 1];
                unsigned short h0, l0, h1, l1;
#pragma unroll
                for (int half = 0; half < 2; half++) {
                    int mm = m + half * 8;
                    split2(acc[i][j][half * 2 + 0] + b0, h0, l0);
                    split2(acc[i][j][half * 2 + 1] + b1, h1, l1);
                    long long a = (long long)mm * p.oRow + n;
                    *(ushort2*)(o0 + a) = make_ushort2(h0, h1);
                    *(ushort2*)(o1 + a) = make_ushort2(l0, l1);
                }
            }
    } else {  // mode 1: transposed hi/lo (vT) via smem staging, coalesced stores
        uint32_t* stg = (uint32_t*)smem;        // [128][129]
#pragma unroll
        for (int i = 0; i < 2; i++)
#pragma unroll
            for (int j = 0; j < 8; j++)
#pragma unroll
                for (int r = 0; r < 4; r++) {
                    int ml = wm * 32 + i * 16 + (r >> 1) * 8 + (lane >> 2);
                    int nl = wn * 64 + j * 8 + (lane & 3) * 2 + (r & 1);
                    float v = acc[i][j][r] + p.bias[bn + nl];
                    unsigned short h, l;
                    split2(v, h, l);
                    stg[ml * 129 + nl] = (uint32_t)h | ((uint32_t)l << 16);
                }
        __syncthreads();
        __nv_bfloat16* o0 = (__nv_bfloat16*)p.out0;
        __nv_bfloat16* o1 = (__nv_bfloat16*)p.out1;
        int col = tid >> 1, r0 = (tid & 1) * 64;
        long long base = (long long)(bn + col) * p.oRow + bm + r0;
#pragma unroll
        for (int r = 0; r < 64; r += 2) {
            uint32_t w0 = stg[(r0 + r) * 129 + col];
            uint32_t w1 = stg[(r0 + r + 1) * 129 + col];
            *(ushort2*)(o0 + base + r) = make_ushort2((unsigned short)(w0 & 0xFFFF),
                                                      (unsigned short)(w1 & 0xFFFF));
            *(ushort2*)(o1 + base + r) = make_ushort2((unsigned short)(w0 >> 16),
                                                      (unsigned short)(w1 >> 16));
        }
    }
}

// ---------------- positional encoding ---------------------------------------
__global__ void pe_kernel(float* __restrict__ pe) {
    int idx = blockIdx.x * blockDim.x + threadIdx.x;
    if (idx >= S_DIM * H_DIM) return;
    int h = idx & (H_DIM - 1);
    int s = idx >> 9;
    int j = (h < H_DIM / 2) ? h : h - H_DIM / 2;
    double d   = exp(-((double)(2 * j)) * (log(10000.0) / (double)H_DIM));
    double ang = (double)s * d;
    pe[idx] = (float)((h < H_DIM / 2) ? sin(ang) : cos(ang));
}

__global__ void conv_x_kernel(const float* __restrict__ in, const float* __restrict__ pe,
                              __nv_bfloat16* __restrict__ xh, __nv_bfloat16* __restrict__ xl) {
    int i = blockIdx.x * blockDim.x + threadIdx.x;
    if (i >= NROWS * H_DIM) return;
    float v = in[i] + pe[i & (S_DIM * H_DIM - 1)];
    unsigned short h, l;
    split2(v, h, l);
    xh[i] = __ushort_as_bfloat16(h);
    xl[i] = __ushort_as_bfloat16(l);
}

__global__ void conv_w_kernel(const float* __restrict__ w,
                              __nv_bfloat16* __restrict__ wh, __nv_bfloat16* __restrict__ wl) {
    int i = blockIdx.x * blockDim.x + threadIdx.x;
    if (i >= H_DIM * H_DIM) return;
    unsigned short h, l;
    split2(w[i], h, l);
    wh[i] = __ushort_as_bfloat16(h);
    wl[i] = __ushort_as_bfloat16(l);
}

// ---------------- softmax: fp32 in, bf16 hi/lo out ---------------------------
__global__ __launch_bounds__(256) void softmax_kernel(const float* __restrict__ sc,
                                                      __nv_bfloat16* __restrict__ ph,
                                                      __nv_bfloat16* __restrict__ pl) {
    const float* row = sc + (long long)blockIdx.x * S_DIM;
    long long obase = (long long)blockIdx.x * S_DIM;
    int tid = threadIdx.x;
    __shared__ float red[256];

    float vals[8];
    float m = -INFINITY;
#pragma unroll
    for (int i = 0; i < 8; i++) { vals[i] = row[tid + i * 256]; m = fmaxf(m, vals[i]); }
    red[tid] = m; __syncthreads();
    for (int s = 128; s > 0; s >>= 1) {
        if (tid < s) red[tid] = fmaxf(red[tid], red[tid + s]);
        __syncthreads();
    }
    m = red[0]; __syncthreads();

    float sum = 0.f;
#pragma unroll
    for (int i = 0; i < 8; i++) { vals[i] = expf(vals[i] - m); sum += vals[i]; }
    red[tid] = sum; __syncthreads();
    for (int s = 128; s > 0; s >>= 1) {
        if (tid < s) red[tid] += red[tid + s];
        __syncthreads();
    }
    float inv = 1.f / red[0];
#pragma unroll
    for (int i = 0; i < 8; i++) {
        float w = vals[i] * inv;
        unsigned short h, l;
        split2(w, h, l);
        ph[obase + tid + i * 256] = __ushort_as_bfloat16(h);
        pl[obase + tid + i * 256] = __ushort_as_bfloat16(l);
    }
}

// ---------------- launch ----------------------------------------------------
extern "C" void kernel_launch(void* const* d_in, const int* in_sizes, int n_in,
                              void* d_out, int out_size) {
    const float* in_e = (const float*)d_in[0];
    const float* Wq   = (const float*)d_in[1];
    const float* bq   = (const float*)d_in[2];
    const float* Wk   = (const float*)d_in[3];
    const float* bk   = (const float*)d_in[4];
    const float* Wv   = (const float*)d_in[5];
    const float* bv   = (const float*)d_in[6];
    float* out = (float*)d_out;

    cudaFuncSetAttribute(tc_gemm, cudaFuncAttributeMaxDynamicSharedMemorySize, SMEM_DYN);

#define SYM(v, s) void* v##_; cudaGetSymbolAddress(&v##_, s);
    SYM(pe, g_pe) SYM(xh, g_xh) SYM(xl, g_xl)
    SYM(wqh, g_wqh) SYM(wql, g_wql) SYM(wkh, g_wkh) SYM(wkl, g_wkl)
    SYM(wvh, g_wvh) SYM(wvl, g_wvl)
    SYM(qh, g_qh) SYM(ql, g_ql) SYM(kh, g_kh) SYM(kl, g_kl)
    SYM(vth, g_vth) SYM(vtl, g_vtl)
    SYM(sc, g_sc) SYM(sph, g_ph) SYM(spl, g_pl)
#undef SYM

    pe_kernel<<<(S_DIM * H_DIM + 255) / 256, 256>>>((float*)pe_);
    conv_x_kernel<<<(NROWS * H_DIM + 255) / 256, 256>>>(in_e, (float*)pe_,
        (__nv_bfloat16*)xh_, (__nv_bfloat16*)xl_);
    conv_w_kernel<<<(H_DIM * H_DIM + 255) / 256, 256>>>(Wq, (__nv_bfloat16*)wqh_, (__nv_bfloat16*)wql_);
    conv_w_kernel<<<(H_DIM * H_DIM + 255) / 256, 256>>>(Wk, (__nv_bfloat16*)wkh_, (__nv_bfloat16*)wkl_);
    conv_w_kernel<<<(H_DIM * H_DIM + 255) / 256, 256>>>(Wv, (__nv_bfloat16*)wvh_, (__nv_bfloat16*)wvl_);

    GemmParams p;
    // Q/K projections: M=16384, N=512, K=512 (mode 0)
    p.Ah = (const __nv_bfloat16*)xh_; p.Al = (const __nv_bfloat16*)xl_;
    p.aBatch = 0; p.bBatch = 0; p.aRow = H_DIM; p.bRow = H_DIM; p.K = H_DIM;
    p.oBatch = 0; p.oRow = H_DIM; p.mode = 0;
    dim3 gq(H_DIM / 128, NROWS / 128, 1);

    p.Bh = (const __nv_bfloat16*)wqh_; p.Bl = (const __nv_bfloat16*)wql_;
    p.bias = bq; p.out0 = qh_; p.out1 = ql_;
    tc_gemm<<<gq, 256, SMEM_DYN>>>(p);

    p.Bh = (const __nv_bfloat16*)wkh_; p.Bl = (const __nv_bfloat16*)wkl_;
    p.bias = bk; p.out0 = kh_; p.out1 = kl_;
    tc_gemm<<<gq, 256, SMEM_DYN>>>(p);

    // V projection, transposed output vT[512][16384] (mode 1)
    p.Bh = (const __nv_bfloat16*)wvh_; p.Bl = (const __nv_bfloat16*)wvl_;
    p.bias = bv; p.out0 = vth_; p.out1 = vtl_;
    p.oRow = NROWS; p.mode = 1;
    tc_gemm<<<gq, 256, SMEM_DYN>>>(p);

    // scores = q @ k^T per batch (mode 2)
    p.Ah = (const __nv_bfloat16*)qh_; p.Al = (const __nv_bfloat16*)ql_;
    p.Bh = (const __nv_bfloat16*)kh_; p.Bl = (const __nv_bfloat16*)kl_;
    p.bias = nullptr;
    p.aBatch = (long long)S_DIM * H_DIM; p.bBatch = (long long)S_DIM * H_DIM;
    p.aRow = H_DIM; p.bRow = H_DIM; p.K = H_DIM;
    p.out0 = sc_; p.out1 = nullptr;
    p.oBatch = (long long)S_DIM * S_DIM; p.oRow = S_DIM; p.mode = 2;
    dim3 gs(S_DIM / 128, S_DIM / 128, B_DIM);
    tc_gemm<<<gs, 256, SMEM_DYN>>>(p);

    // softmax -> bf16 hi/lo probs
    softmax_kernel<<<B_DIM * S_DIM, 256>>>((const float*)sc_,
        (__nv_bfloat16*)sph_, (__nv_bfloat16*)spl_);

    // out = probs @ v : NT with B = vT (mode 2 fp32 out)
    p.Ah = (const __nv_bfloat16*)sph_; p.Al = (const __nv_bfloat16*)spl_;
    p.Bh = (const __nv_bfloat16*)vth_; p.Bl = (const __nv_bfloat16*)vtl_;
    p.bias = nullptr;
    p.aBatch = (long long)S_DIM * S_DIM; p.bBatch = S_DIM;
    p.aRow = S_DIM; p.bRow = NROWS; p.K = S_DIM;
    p.out0 = out; p.out1 = nullptr;
    p.oBatch = (long long)S_DIM * H_DIM; p.oRow = H_DIM; p.mode = 2;
    dim3 go(H_DIM / 128, S_DIM / 128, B_DIM);
    tc_gemm<<<go, 256, SMEM_DYN>>>(p);
}

// round 5
// speedup vs baseline: 2.4222x; 1.1211x over previous
#include <cuda_runtime.h>
#include <cuda_fp16.h>
#include <cstdint>
#include <math.h>

#define B_DIM 8
#define S_DIM 2048
#define H_DIM 512
#define NROWS (B_DIM * S_DIM)          // 16384

// ---------------- scratch (device globals; no allocations allowed) ----------
__device__ float g_pe[S_DIM * H_DIM];
__device__ __half g_xh[NROWS * H_DIM], g_xl[NROWS * H_DIM];
__device__ __half g_wqh[H_DIM * H_DIM], g_wql[H_DIM * H_DIM];
__device__ __half g_wkh[H_DIM * H_DIM], g_wkl[H_DIM * H_DIM];
__device__ __half g_wvh[H_DIM * H_DIM], g_wvl[H_DIM * H_DIM];
__device__ __half g_qh[NROWS * H_DIM], g_ql[NROWS * H_DIM];
__device__ __half g_kh[NROWS * H_DIM], g_kl[NROWS * H_DIM];
__device__ __half g_vth[H_DIM * NROWS], g_vtl[H_DIM * NROWS];   // v transposed
__device__ float g_sc[(long long)B_DIM * S_DIM * S_DIM];        // 134 MB
__device__ __half g_ph[(long long)B_DIM * S_DIM * S_DIM];       // probs, single fp16

// ---------------- helpers ----------------------------------------------
__device__ __forceinline__ uint32_t smem_u32(const void* p) {
    uint32_t a;
    asm("{ .reg .u64 t; cvta.to.shared.u64 t, %1; cvt.u32.u64 %0, t; }" : "=r"(a) : "l"(p));
    return a;
}
__device__ __forceinline__ void cp16(uint32_t dst, const void* src) {
    asm volatile("cp.async.cg.shared.global [%0], [%1], 16;"
                 :: "r"(dst), "l"(__cvta_generic_to_global(src)));
}
#define CP_COMMIT() asm volatile("cp.async.commit_group;" ::: "memory")
#define CP_WAIT_1() asm volatile("cp.async.wait_group 1;" ::: "memory")
#define CP_WAIT_0() asm volatile("cp.async.wait_group 0;" ::: "memory")

__device__ __forceinline__ void ldsm4(uint32_t& r0, uint32_t& r1, uint32_t& r2, uint32_t& r3,
                                      uint32_t addr) {
    asm volatile("ldmatrix.sync.aligned.m8n8.x4.shared.b16 {%0,%1,%2,%3}, [%4];"
                 : "=r"(r0), "=r"(r1), "=r"(r2), "=r"(r3) : "r"(addr));
}
__device__ __forceinline__ void mma16816(float* c, const uint32_t* a, const uint32_t* b) {
    asm volatile(
        "mma.sync.aligned.m16n8k16.row.col.f32.f16.f16.f32 "
        "{%0,%1,%2,%3}, {%4,%5,%6,%7}, {%8,%9}, {%0,%1,%2,%3};"
        : "+f"(c[0]), "+f"(c[1]), "+f"(c[2]), "+f"(c[3])
        : "r"(a[0]), "r"(a[1]), "r"(a[2]), "r"(a[3]), "r"(b[0]), "r"(b[1]));
}
__device__ __forceinline__ void split2h(float v, unsigned short& h, unsigned short& l) {
    __half hh = __float2half_rn(v);
    __half ll = __float2half_rn(v - __half2float(hh));
    h = __half_as_ushort(hh);
    l = __half_as_ushort(ll);
}

// ---------------- split-fp16 HMMA GEMM: C = A * B^T -------------------------
// A[M,K], B[N,K] K-major fp16. 128x128 tile, BK=32, 256 thr, warp 32x64.
// NPROD=3: A,B both hi/lo (4 tiles). NPROD=2: A single, B hi/lo (3 tiles).
struct GemmParams {
    const __half *Ah, *Al, *Bh, *Bl;
    const float* bias;
    long long aBatch, bBatch;
    int aRow, bRow;
    int K;
    void* out0; void* out1;
    long long oBatch;
    int oRow;
};

#define ROW_PITCH   80
#define TILE_BYTES  (128 * ROW_PITCH)       // 10240

template<int NPROD, int MODE>   // MODE: 0=bias+hi/lo, 1=bias+hi/lo transposed, 2=fp32
__global__ __launch_bounds__(256, 2) void tc_gemm(GemmParams p) {
    constexpr int NT = (NPROD == 3) ? 4 : 3;
    constexpr int STAGE = NT * TILE_BYTES;
    extern __shared__ char smem[];
    uint32_t sbase = smem_u32(smem);

    const int tid = threadIdx.x;
    const int wid = tid >> 5, lane = tid & 31;
    const int wm = wid & 3, wn = wid >> 2;          // warp tile (wm*32, wn*64)

    const int bm = blockIdx.y * 128, bn = blockIdx.x * 128, z = blockIdx.z;
    const __half* Ah = p.Ah + (long long)z * p.aBatch;
    const __half* Al = p.Al + (long long)z * p.aBatch;
    const __half* Bh = p.Bh + (long long)z * p.bBatch;
    const __half* Bl = p.Bl + (long long)z * p.bBatch;
    const int aRow = p.aRow, bRow = p.bRow;

    const int nc = p.K >> 5;   // chunks of 32

    auto load_chunk = [&](int c, int s) {
        uint32_t stBase = sbase + s * STAGE;
        long long kofs = (long long)c * 32;
#pragma unroll
        for (int t = 0; t < NT; t++) {
            const __half* src;
            int rbase, rstride;
            if (NPROD == 3) {
                if (t == 0)      { src = Ah; rbase = bm; rstride = aRow; }
                else if (t == 1) { src = Al; rbase = bm; rstride = aRow; }
                else if (t == 2) { src = Bh; rbase = bn; rstride = bRow; }
                else             { src = Bl; rbase = bn; rstride = bRow; }
            } else {
                if (t == 0)      { src = Ah; rbase = bm; rstride = aRow; }
                else if (t == 1) { src = Bh; rbase = bn; rstride = bRow; }
                else             { src = Bl; rbase = bn; rstride = bRow; }
            }
#pragma unroll
            for (int it = 0; it < 2; it++) {
                int u = tid + it * 256;              // 512 chunk units
                int row = u >> 2, ch = u & 3;
                const void* g = src + (long long)(rbase + row) * rstride + kofs + ch * 8;
                uint32_t off = row * ROW_PITCH + ch * 16;
                cp16(stBase + t * TILE_BYTES + off, g);
            }
        }
        CP_COMMIT();
    };

    float acc[2][8][4];
#pragma unroll
    for (int i = 0; i < 2; i++)
#pragma unroll
        for (int j = 0; j < 8; j++)
#pragma unroll
            for (int r = 0; r < 4; r++) acc[i][j][r] = 0.f;

    load_chunk(0, 0);
    if (nc > 1) load_chunk(1, 1);

    for (int c = 0; c < nc; c++) {
        int s = c & 1;
        if (c == nc - 1) CP_WAIT_0(); else CP_WAIT_1();
        __syncthreads();

        uint32_t st = sbase + s * STAGE;
        uint32_t aHB = st;
        uint32_t aLB = st + TILE_BYTES;                       // only if NPROD==3
        uint32_t bHB = st + (NT - 2) * TILE_BYTES;
        uint32_t bLB = st + (NT - 1) * TILE_BYTES;

#pragma unroll
        for (int ks = 0; ks < 2; ks++) {
            const int chcol = (ks * 2 + (lane >> 4)) * 16;
            uint32_t ah[2][4], al[2][4];
#pragma unroll
            for (int t = 0; t < 2; t++) {
                int row = wm * 32 + t * 16 + (lane & 15);
                uint32_t off = row * ROW_PITCH + chcol;
                ldsm4(ah[t][0], ah[t][1], ah[t][2], ah[t][3], aHB + off);
                if (NPROD == 3)
                    ldsm4(al[t][0], al[t][1], al[t][2], al[t][3], aLB + off);
            }
#pragma unroll
            for (int jh = 0; jh < 2; jh++) {
                uint32_t bh[4][2], bl[4][2];
#pragma unroll
                for (int jj = 0; jj < 2; jj++) {
                    int row = wn * 64 + (jh * 2 + jj) * 16 + (lane & 15);
                    uint32_t off = row * ROW_PITCH + chcol;
                    uint32_t r0, r1, r2, r3;
                    ldsm4(r0, r1, r2, r3, bHB + off);
                    bh[jj * 2][0] = r0; bh[jj * 2][1] = r2;
                    bh[jj * 2 + 1][0] = r1; bh[jj * 2 + 1][1] = r3;
                    ldsm4(r0, r1, r2, r3, bLB + off);
                    bl[jj * 2][0] = r0; bl[jj * 2][1] = r2;
                    bl[jj * 2 + 1][0] = r1; bl[jj * 2 + 1][1] = r3;
                }
                // product-major ordering: dependent acc updates 8 MMAs apart
#pragma unroll
                for (int i = 0; i < 2; i++)
#pragma unroll
                    for (int j4 = 0; j4 < 4; j4++)
                        mma16816(acc[i][jh * 4 + j4], ah[i], bh[j4]);
#pragma unroll
                for (int i = 0; i < 2; i++)
#pragma unroll
                    for (int j4 = 0; j4 < 4; j4++)
                        mma16816(acc[i][jh * 4 + j4], ah[i], bl[j4]);
                if (NPROD == 3) {
#pragma unroll
                    for (int i = 0; i < 2; i++)
#pragma unroll
                        for (int j4 = 0; j4 < 4; j4++)
                            mma16816(acc[i][jh * 4 + j4], al[i], bh[j4]);
                }
            }
        }
        __syncthreads();
        if (c + 2 < nc) load_chunk(c + 2, s);
    }

    // --------- epilogue ---------
    const int mB = bm + wm * 32 + (lane >> 2);
    const int nB = bn + wn * 64 + (lane & 3) * 2;

    if (MODE == 2) {
        float* o0 = (float*)p.out0 + (long long)z * p.oBatch;
#pragma unroll
        for (int i = 0; i < 2; i++)
#pragma unroll
            for (int j = 0; j < 8; j++) {
                int m = mB + i * 16, n = nB + j * 8;
                *(float2*)(o0 + (long long)m * p.oRow + n)       = make_float2(acc[i][j][0], acc[i][j][1]);
                *(float2*)(o0 + (long long)(m + 8) * p.oRow + n) = make_float2(acc[i][j][2], acc[i][j][3]);
            }
    } else if (MODE == 0) {
        __half* o0 = (__half*)p.out0;
        __half* o1 = (__half*)p.out1;
#pragma unroll
        for (int i = 0; i < 2; i++)
#pragma unroll
            for (int j = 0; j < 8; j++) {
                int m = mB + i * 16, n = nB + j * 8;
                float b0 = p.bias[n], b1 = p.bias[n + 1];
                unsigned short h0, l0, h1, l1;
#pragma unroll
                for (int half_ = 0; half_ < 2; half_++) {
                    int mm = m + half_ * 8;
                    split2h(acc[i][j][half_ * 2 + 0] + b0, h0, l0);
                    split2h(acc[i][j][half_ * 2 + 1] + b1, h1, l1);
                    long long a = (long long)mm * p.oRow + n;
                    *(ushort2*)(o0 + a) = make_ushort2(h0, h1);
                    *(ushort2*)(o1 + a) = make_ushort2(l0, l1);
                }
            }
    } else {  // MODE 1: transposed hi/lo (vT) via smem staging, coalesced stores
        uint32_t* stg = (uint32_t*)smem;        // [128][129]
#pragma unroll
        for (int i = 0; i < 2; i++)
#pragma unroll
            for (int j = 0; j < 8; j++)
#pragma unroll
                for (int r = 0; r < 4; r++) {
                    int ml = wm * 32 + i * 16 + (r >> 1) * 8 + (lane >> 2);
                    int nl = wn * 64 + j * 8 + (lane & 3) * 2 + (r & 1);
                    float v = acc[i][j][r] + p.bias[bn + nl];
                    unsigned short h, l;
                    split2h(v, h, l);
                    stg[ml * 129 + nl] = (uint32_t)h | ((uint32_t)l << 16);
                }
        __syncthreads();
        __half* o0 = (__half*)p.out0;
        __half* o1 = (__half*)p.out1;
        int col = tid >> 1, r0 = (tid & 1) * 64;
        long long base = (long long)(bn + col) * p.oRow + bm + r0;
#pragma unroll
        for (int r = 0; r < 64; r += 2) {
            uint32_t w0 = stg[(r0 + r) * 129 + col];
            uint32_t w1 = stg[(r0 + r + 1) * 129 + col];
            *(ushort2*)(o0 + base + r) = make_ushort2((unsigned short)(w0 & 0xFFFF),
                                                      (unsigned short)(w1 & 0xFFFF));
            *(ushort2*)(o1 + base + r) = make_ushort2((unsigned short)(w0 >> 16),
                                                      (unsigned short)(w1 >> 16));
        }
    }
}

// ---------------- prep: pe table + weight splits (one launch) ---------------
__global__ void prep_kernel(const float* __restrict__ Wq, const float* __restrict__ Wk,
                            const float* __restrict__ Wv,
                            float* __restrict__ pe,
                            __half* __restrict__ wqh, __half* __restrict__ wql,
                            __half* __restrict__ wkh, __half* __restrict__ wkl,
                            __half* __restrict__ wvh, __half* __restrict__ wvl) {
    int b = blockIdx.x;
    int t = threadIdx.x;
    if (b < 4096) {                                    // pe: 1M elements
        int idx = b * 256 + t;
        int h = idx & (H_DIM - 1);
        int s = idx >> 9;
        int j = (h < H_DIM / 2) ? h : h - H_DIM / 2;
        double d   = exp(-((double)(2 * j)) * (log(10000.0) / (double)H_DIM));
        double ang = (double)s * d;
        pe[idx] = (float)((h < H_DIM / 2) ? sin(ang) : cos(ang));
    } else {                                           // weight splits: 3 x 256K
        int w = (b - 4096) >> 10;                      // 1024 blocks per weight
        int idx = ((b - 4096) & 1023) * 256 + t;
        const float* W = (w == 0) ? Wq : (w == 1) ? Wk : Wv;
        __half* oh = (w == 0) ? wqh : (w == 1) ? wkh : wvh;
        __half* ol = (w == 0) ? wql : (w == 1) ? wkl : wvl;
        unsigned short h, l;
        split2h(W[idx], h, l);
        oh[idx] = __ushort_as_half(h);
        ol[idx] = __ushort_as_half(l);
    }
}

__global__ void conv_x_kernel(const float* __restrict__ in, const float* __restrict__ pe,
                              __half* __restrict__ xh, __half* __restrict__ xl) {
    int i = blockIdx.x * blockDim.x + threadIdx.x;
    if (i >= NROWS * H_DIM) return;
    float v = in[i] + pe[i & (S_DIM * H_DIM - 1)];
    unsigned short h, l;
    split2h(v, h, l);
    xh[i] = __ushort_as_half(h);
    xl[i] = __ushort_as_half(l);
}

// ---------------- softmax: fp32 in, single fp16 out --------------------------
__global__ __launch_bounds__(256) void softmax_kernel(const float* __restrict__ sc,
                                                      __half* __restrict__ ph) {
    const float* row = sc + (long long)blockIdx.x * S_DIM;
    long long obase = (long long)blockIdx.x * S_DIM;
    int tid = threadIdx.x;
    __shared__ float red[256];

    float vals[8];
    float m = -INFINITY;
#pragma unroll
    for (int i = 0; i < 8; i++) { vals[i] = row[tid + i * 256]; m = fmaxf(m, vals[i]); }
    red[tid] = m; __syncthreads();
    for (int s = 128; s > 0; s >>= 1) {
        if (tid < s) red[tid] = fmaxf(red[tid], red[tid + s]);
        __syncthreads();
    }
    m = red[0]; __syncthreads();

    float sum = 0.f;
#pragma unroll
    for (int i = 0; i < 8; i++) { vals[i] = expf(vals[i] - m); sum += vals[i]; }
    red[tid] = sum; __syncthreads();
    for (int s = 128; s > 0; s >>= 1) {
        if (tid < s) red[tid] += red[tid + s];
        __syncthreads();
    }
    float inv = 1.f / red[0];
#pragma unroll
    for (int i = 0; i < 4; i++) {
        __half2 w2 = __floats2half2_rn(vals[i * 2] * inv, vals[i * 2 + 1] * inv);
        // interleaved pairs: positions tid*... keep original layout: write separately
        ph[obase + tid + (i * 2) * 256]     = __low2half(w2);
        ph[obase + tid + (i * 2 + 1) * 256] = __high2half(w2);
    }
}

// ---------------- launch ----------------------------------------------------
extern "C" void kernel_launch(void* const* d_in, const int* in_sizes, int n_in,
                              void* d_out, int out_size) {
    const float* in_e = (const float*)d_in[0];
    const float* Wq   = (const float*)d_in[1];
    const float* bq   = (const float*)d_in[2];
    const float* Wk   = (const float*)d_in[3];
    const float* bk   = (const float*)d_in[4];
    const float* Wv   = (const float*)d_in[5];
    const float* bv   = (const float*)d_in[6];
    float* out = (float*)d_out;

    const int SMEM3 = 2 * 4 * TILE_BYTES;   // 81920
    const int SMEM2 = 2 * 3 * TILE_BYTES;   // 61440
    cudaFuncSetAttribute(tc_gemm<3,0>, cudaFuncAttributeMaxDynamicSharedMemorySize, SMEM3);
    cudaFuncSetAttribute(tc_gemm<3,1>, cudaFuncAttributeMaxDynamicSharedMemorySize, SMEM3);
    cudaFuncSetAttribute(tc_gemm<3,2>, cudaFuncAttributeMaxDynamicSharedMemorySize, SMEM3);
    cudaFuncSetAttribute(tc_gemm<2,2>, cudaFuncAttributeMaxDynamicSharedMemorySize, SMEM2);

#define SYM(v, s) void* v##_; cudaGetSymbolAddress(&v##_, s);
    SYM(pe, g_pe) SYM(xh, g_xh) SYM(xl, g_xl)
    SYM(wqh, g_wqh) SYM(wql, g_wql) SYM(wkh, g_wkh) SYM(wkl, g_wkl)
    SYM(wvh, g_wvh) SYM(wvl, g_wvl)
    SYM(qh, g_qh) SYM(ql, g_ql) SYM(kh, g_kh) SYM(kl, g_kl)
    SYM(vth, g_vth) SYM(vtl, g_vtl)
    SYM(sc, g_sc) SYM(sph, g_ph)
#undef SYM

    // launch 0: prep (pe + all 3 weight splits)
    prep_kernel<<<4096 + 3072, 256>>>(Wq, Wk, Wv, (float*)pe_,
        (__half*)wqh_, (__half*)wql_, (__half*)wkh_, (__half*)wkl_,
        (__half*)wvh_, (__half*)wvl_);
    // launch 1: x = embeds + pe, split
    conv_x_kernel<<<(NROWS * H_DIM + 255) / 256, 256>>>(in_e, (float*)pe_,
        (__half*)xh_, (__half*)xl_);

    GemmParams p;
    p.Ah = (const __half*)xh_; p.Al = (const __half*)xl_;
    p.aBatch = 0; p.bBatch = 0; p.aRow = H_DIM; p.bRow = H_DIM; p.K = H_DIM;
    p.oBatch = 0; p.oRow = H_DIM;
    dim3 gq(H_DIM / 128, NROWS / 128, 1);

    // launch 2: Q
    p.Bh = (const __half*)wqh_; p.Bl = (const __half*)wql_;
    p.bias = bq; p.out0 = qh_; p.out1 = ql_;
    tc_gemm<3,0><<<gq, 256, SMEM3>>>(p);
    // launch 3: K
    p.Bh = (const __half*)wkh_; p.Bl = (const __half*)wkl_;
    p.bias = bk; p.out0 = kh_; p.out1 = kl_;
    tc_gemm<3,0><<<gq, 256, SMEM3>>>(p);
    // launch 4: V (transposed out)
    p.Bh = (const __half*)wvh_; p.Bl = (const __half*)wvl_;
    p.bias = bv; p.out0 = vth_; p.out1 = vtl_;
    p.oRow = NROWS;
    tc_gemm<3,1><<<gq, 256, SMEM3>>>(p);

    // launch 5: scores = q @ k^T  (captured by ncu -s 5)
    p.Ah = (const __half*)qh_; p.Al = (const __half*)ql_;
    p.Bh = (const __half*)kh_; p.Bl = (const __half*)kl_;
    p.bias = nullptr;
    p.aBatch = (long long)S_DIM * H_DIM; p.bBatch = (long long)S_DIM * H_DIM;
    p.aRow = H_DIM; p.bRow = H_DIM; p.K = H_DIM;
    p.out0 = sc_; p.out1 = nullptr;
    p.oBatch = (long long)S_DIM * S_DIM; p.oRow = S_DIM;
    dim3 gs(S_DIM / 128, S_DIM / 128, B_DIM);
    tc_gemm<3,2><<<gs, 256, SMEM3>>>(p);

    // launch 6: softmax -> single fp16 probs
    softmax_kernel<<<B_DIM * S_DIM, 256>>>((const float*)sc_, (__half*)sph_);

    // launch 7: out = probs @ v  (2-product: ph*vh + ph*vl)
    p.Ah = (const __half*)sph_; p.Al = nullptr;
    p.Bh = (const __half*)vth_; p.Bl = (const __half*)vtl_;
    p.bias = nullptr;
    p.aBatch = (long long)S_DIM * S_DIM; p.bBatch = S_DIM;
    p.aRow = S_DIM; p.bRow = NROWS; p.K = S_DIM;
    p.out0 = out; p.out1 = nullptr;
    p.oBatch = (long long)S_DIM * H_DIM; p.oRow = H_DIM;
    dim3 go(H_DIM / 128, S_DIM / 128, B_DIM);
    tc_gemm<2,2><<<go, 256, SMEM2>>>(p);
}